// round 11
// baseline (speedup 1.0000x reference)
#include <cuda_runtime.h>
#include <cuda_bf16.h>
#include <cstdint>

#define M_TOTAL 8192
#define K_TOTAL 4608
#define N_TOTAL 4608
#define GSIZE   36

// -------- device scratch (static: no allocation in kernel_launch) --------
__device__ __nv_bfloat16 g_qx[(size_t)M_TOTAL * K_TOTAL];  // 75.5 MB
__device__ __nv_bfloat16 g_qw[(size_t)N_TOTAL * K_TOTAL];  // 42.5 MB
__device__ int g_tile_ctr;                                  // work-steal counter

// ============================ helpers ============================
__device__ __forceinline__ uint32_t smem_u32(const void* p) {
    uint32_t a;
    asm("{ .reg .u64 t; cvta.to.shared.u64 t, %1; cvt.u32.u64 %0, t; }"
        : "=r"(a) : "l"(p));
    return a;
}

#define SW128(o) ((o) ^ (((o) >> 3) & 0x70))

__device__ __forceinline__ void cp16(uint32_t saddr, const void* g) {
    asm volatile("cp.async.cg.shared.global [%0], [%1], 16;"
                 :: "r"(saddr), "l"(g) : "memory");
}
#define CP_COMMIT() asm volatile("cp.async.commit_group;" ::: "memory")
#define CP_WAIT0()  asm volatile("cp.async.wait_group 0;" ::: "memory")
#define CP_WAIT1()  asm volatile("cp.async.wait_group 1;" ::: "memory")

#define LDSM_X4(r, addr) \
    asm volatile("ldmatrix.sync.aligned.m8n8.x4.shared.b16 {%0,%1,%2,%3}, [%4];" \
        : "=r"((r)[0]), "=r"((r)[1]), "=r"((r)[2]), "=r"((r)[3]) : "r"(addr))

#define MMA16816(d, a, b0, b1) \
    asm volatile("mma.sync.aligned.m16n8k16.row.col.f32.bf16.bf16.f32 " \
        "{%0,%1,%2,%3}, {%4,%5,%6,%7}, {%8,%9}, {%0,%1,%2,%3};" \
        : "+f"((d)[0]), "+f"((d)[1]), "+f"((d)[2]), "+f"((d)[3]) \
        : "r"((a)[0]), "r"((a)[1]), "r"((a)[2]), "r"((a)[3]), "r"(b0), "r"(b1))

// ============================ Quantize ============================
// Single launch over BOTH tensors. Block-staged, 256 groups per block.
// Exact: power-of-two scaling, <=8 significand bits -> exact in bf16.
// Block 0 also resets the GEMM work-steal counter (quant precedes GEMM
// on the same stream, so this is ordered and replay-deterministic).
#define NBLK_IN ((M_TOTAL * K_TOTAL) / (GSIZE * 256))   // 4096
#define NBLK_W  ((N_TOTAL * K_TOTAL) / (GSIZE * 256))   // 2304
#define GRID_GEMM 296

__global__ void __launch_bounds__(256) bfp_quant(const float* __restrict__ inp,
                                                 const float* __restrict__ wgt,
                                                 __nv_bfloat16* __restrict__ qx,
                                                 __nv_bfloat16* __restrict__ qw) {
    __shared__ float s[9216];
    const int tid = threadIdx.x;
    const int blk = blockIdx.x;
    if (blk == 0 && tid == 0) g_tile_ctr = GRID_GEMM;
    const bool is_w = (blk >= NBLK_IN);
    const float* in = is_w ? wgt : inp;
    __nv_bfloat16* out = is_w ? qw : qx;
    const size_t base = (size_t)(is_w ? blk - NBLK_IN : blk) * 9216;

    const float4* in4 = (const float4*)(in + base);
    float4* s4 = (float4*)s;
    #pragma unroll
    for (int j = 0; j < 9; ++j)
        s4[j * 256 + tid] = in4[j * 256 + tid];
    __syncthreads();

    float4 v[9];
    const float4* g4 = (const float4*)(s + tid * GSIZE);
    float m = 0.0f;
    #pragma unroll
    for (int i = 0; i < 9; ++i) {
        v[i] = g4[i];
        m = fmaxf(m, fmaxf(fmaxf(fabsf(v[i].x), fabsf(v[i].y)),
                           fmaxf(fabsf(v[i].z), fabsf(v[i].w))));
    }
    if (m > 0.0f) {
        int e = (int)((__float_as_uint(m) >> 23) & 0xFF) - 127;
        float stp = __int_as_float((uint32_t)(e - 7 + 127) << 23);  // 2^(e-7)
        float inv = __int_as_float((uint32_t)(7 - e + 127) << 23);  // 2^(7-e)
        #pragma unroll
        for (int i = 0; i < 9; ++i) {
            v[i].x = truncf(v[i].x * inv) * stp;
            v[i].y = truncf(v[i].y * inv) * stp;
            v[i].z = truncf(v[i].z * inv) * stp;
            v[i].w = truncf(v[i].w * inv) * stp;
        }
    }
    __syncthreads();   // all reads of s done before overwrite

    __nv_bfloat162* s2 = (__nv_bfloat162*)s;
    #pragma unroll
    for (int i = 0; i < 9; ++i) {
        s2[tid * 18 + 2 * i]     = __nv_bfloat162(__float2bfloat16(v[i].x),
                                                  __float2bfloat16(v[i].y));
        s2[tid * 18 + 2 * i + 1] = __nv_bfloat162(__float2bfloat16(v[i].z),
                                                  __float2bfloat16(v[i].w));
    }
    __syncthreads();

    uint4* o4 = (uint4*)(out + base);
    const uint4* so4 = (const uint4*)s;
    #pragma unroll
    for (int j = 0; j < 4; ++j)
        o4[j * 256 + tid] = so4[j * 256 + tid];
    if (tid < 128) o4[1024 + tid] = so4[1024 + tid];
}

// ============================ GEMM ============================
// D = qx @ qw^T + bias   (TN). R10 mainloop (measured best) made
// persistent with WORK-STEALING + CROSS-TILE PIPELINING:
//  - 296 CTAs (2/SM); next tile grabbed via atomicAdd at k-iter 69,
//    broadcast through SMEM, read after the iter-70 barrier.
//  - cp.async ring flows across tiles: iters 70/71 prefetch next tile's
//    k-chunks 0/1. 72 % 3 == 0 keeps stage indices self-aligned.
//  - Wait discipline uniform: WAIT1 always, WAIT0 only on the globally
//    final iteration. Epilogue is register-only, overlapping the
//    in-flight next-tile loads.
#define BM 128
#define BN 128
#define BK 64
#define KITERS (K_TOTAL / BK)       // 72
#define NTILE_N (N_TOTAL / BN)      // 36
#define NTILES  ((M_TOTAL / BM) * NTILE_N)  // 2304
#define A_BYTES 16384               // 128 rows x 128 B
#define B_BYTES 16384
#define STAGE_BYTES (A_BYTES + B_BYTES)   // 32768
#define NSTAGE 3
#define SMEM_BYTES (NSTAGE * STAGE_BYTES + 128)  // + broadcast word

__global__ void __launch_bounds__(256, 2)
bfp_gemm(const float* __restrict__ bias, float* __restrict__ out) {
    extern __shared__ char smem[];
    const uint32_t sb = smem_u32(smem);
    int* snext = (int*)(smem + NSTAGE * STAGE_BYTES);
    const int tid  = threadIdx.x;
    const int wid  = tid >> 5;
    const int lane = tid & 31;

    const int m_warp = (wid & 1) * 64;   // 2 warps along M
    const int n_warp = (wid >> 1) * 32;  // 4 warps along N

    // loader constants
    const int ldr = tid >> 3;        // 0..31
    const int ldc = tid & 7;         // 16B chunk
    const uint32_t soff0 = SW128((uint32_t)(ldr * 128 + ldc * 16));

    auto load_tiles = [&](const __nv_bfloat16* Ap, const __nv_bfloat16* Bp,
                          int kk, int stg) {
        const __nv_bfloat16* Ak = Ap + kk * BK;
        const __nv_bfloat16* Bk = Bp + kk * BK;
        const uint32_t base = sb + (uint32_t)stg * STAGE_BYTES;
        #pragma unroll
        for (int j = 0; j < 4; ++j) {
            int r = ldr + j * 32;
            cp16(base + soff0 + j * 32 * 128,
                 Ak + (size_t)r * K_TOTAL + ldc * 8);
            cp16(base + A_BYTES + soff0 + j * 32 * 128,
                 Bk + (size_t)r * K_TOTAL + ldc * 8);
        }
        CP_COMMIT();
    };

    // ldmatrix lane addressing
    const int r_in  = (lane & 7) + ((lane >> 3) & 1) * 8;
    const int khalf = lane >> 4;

    // SW128(row*128 + bc) == row*128 + (bc ^ ((row&7)<<4)) for bc < 128.
    uint32_t rbA[4], rbB[2];
    #pragma unroll
    for (int im = 0; im < 4; ++im) {
        int r = m_warp + im * 16 + r_in;
        rbA[im] = (uint32_t)(r * 128 + ((r & 7) << 4));
    }
    #pragma unroll
    for (int j2 = 0; j2 < 2; ++j2) {
        int r = n_warp + j2 * 16 + r_in;
        rbB[j2] = (uint32_t)(r * 128 + ((r & 7) << 4));
    }
    const uint32_t bc0 = (uint32_t)(khalf * 16);
    const int row_t = lane >> 2;
    const int col_t = (lane & 3) * 2;

    // ---- persistent setup: first tile = blockIdx.x, counter starts at 296
    int tile = blockIdx.x;
    int m0 = (tile / NTILE_N) * BM;
    int n0 = (tile % NTILE_N) * BN;
    const __nv_bfloat16* Ag = g_qx + (size_t)m0 * K_TOTAL;
    const __nv_bfloat16* Bg = g_qw + (size_t)n0 * K_TOTAL;

    load_tiles(Ag, Bg, 0, 0);
    load_tiles(Ag, Bg, 1, 1);

    int stage = 0;                      // runs continuously; 72 % 3 == 0
    for (;;) {
        float acc[4][4][4];
        #pragma unroll
        for (int i = 0; i < 4; ++i)
            #pragma unroll
            for (int j = 0; j < 4; ++j)
                #pragma unroll
                for (int c = 0; c < 4; ++c) acc[i][j][c] = 0.0f;

        bool has_next = false;
        int next_tile = NTILES;
        const __nv_bfloat16* AgN = Ag;
        const __nv_bfloat16* BgN = Bg;

        for (int it = 0; it < KITERS; ++it) {
            if (it == KITERS - 1 && !has_next) { CP_WAIT0(); }
            else                              { CP_WAIT1(); }
            __syncthreads();   // cp.async data visible; reload slot free

            if (it == KITERS - 3 && tid == 0)
                *snext = atomicAdd(&g_tile_ctr, 1);   // visible after it-70 barrier

            int ls = stage + 2; if (ls >= NSTAGE) ls -= NSTAGE;
            if (it < KITERS - 2) {
                load_tiles(Ag, Bg, it + 2, ls);
            } else {
                if (it == KITERS - 2) {
                    next_tile = *snext;
                    has_next = (next_tile < NTILES);
                    if (has_next) {
                        AgN = g_qx + (size_t)((next_tile / NTILE_N) * BM) * K_TOTAL;
                        BgN = g_qw + (size_t)((next_tile % NTILE_N) * BN) * K_TOTAL;
                    }
                }
                if (has_next)
                    load_tiles(AgN, BgN, it - (KITERS - 2), ls);
            }

            const uint32_t aBase = sb + (uint32_t)stage * STAGE_BYTES;
            const uint32_t bBase = aBase + A_BYTES;

            #pragma unroll
            for (int ks = 0; ks < 4; ++ks) {
                const uint32_t bc = bc0 ^ (uint32_t)(ks * 32);
                uint32_t afr[4][4], bfr[2][4];
                #pragma unroll
                for (int im = 0; im < 4; ++im)
                    LDSM_X4(afr[im], aBase + (rbA[im] ^ bc));
                #pragma unroll
                for (int j2 = 0; j2 < 2; ++j2)
                    LDSM_X4(bfr[j2], bBase + (rbB[j2] ^ bc));
                #pragma unroll
                for (int im = 0; im < 4; ++im)
                    #pragma unroll
                    for (int jn = 0; jn < 4; ++jn)
                        MMA16816(acc[im][jn],
                                 afr[im],
                                 bfr[jn >> 1][jn & 1],
                                 bfr[jn >> 1][(jn & 1) + 2]);
            }
            stage = (stage + 1 == NSTAGE) ? 0 : stage + 1;
        }

        // epilogue: register-only (+bias); next tile's cp.async in flight
        #pragma unroll
        for (int jn = 0; jn < 4; ++jn) {
            const int gn = n0 + n_warp + jn * 8 + col_t;
            const float bx = __ldg(bias + gn);
            const float by = __ldg(bias + gn + 1);
            #pragma unroll
            for (int im = 0; im < 4; ++im) {
                const int gm = m0 + m_warp + im * 16 + row_t;
                float2 v0 = make_float2(acc[im][jn][0] + bx, acc[im][jn][1] + by);
                float2 v1 = make_float2(acc[im][jn][2] + bx, acc[im][jn][3] + by);
                *(float2*)&out[(size_t)gm * N_TOTAL + gn]       = v0;
                *(float2*)&out[(size_t)(gm + 8) * N_TOTAL + gn] = v1;
            }
        }

        if (!has_next) break;
        tile = next_tile;
        m0 = (tile / NTILE_N) * BM;
        n0 = (tile % NTILE_N) * BN;
        Ag = AgN;
        Bg = BgN;
    }
}

// ============================ launch ============================
extern "C" void kernel_launch(void* const* d_in, const int* in_sizes, int n_in,
                              void* d_out, int out_size) {
    const float* inp  = (const float*)d_in[0];
    const float* wgt  = (const float*)d_in[1];
    const float* bias = (const float*)d_in[2];
    float* out = (float*)d_out;

    void *qx_p = nullptr, *qw_p = nullptr;
    cudaGetSymbolAddress(&qx_p, g_qx);
    cudaGetSymbolAddress(&qw_p, g_qw);

    cudaFuncSetAttribute(bfp_gemm, cudaFuncAttributeMaxDynamicSharedMemorySize,
                         SMEM_BYTES);

    bfp_quant<<<NBLK_IN + NBLK_W, 256>>>(inp, wgt,
                                         (__nv_bfloat16*)qx_p,
                                         (__nv_bfloat16*)qw_p);

    bfp_gemm<<<GRID_GEMM, 256, SMEM_BYTES>>>(bias, out);
}

// round 12
// speedup vs baseline: 1.0023x; 1.0023x over previous
#include <cuda_runtime.h>
#include <cuda_bf16.h>
#include <cstdint>

#define M_TOTAL 8192
#define K_TOTAL 4608
#define N_TOTAL 4608
#define GSIZE   36

// -------- device scratch (static: no allocation in kernel_launch) --------
__device__ __nv_bfloat16 g_qx[(size_t)M_TOTAL * K_TOTAL];  // 75.5 MB
__device__ __nv_bfloat16 g_qw[(size_t)N_TOTAL * K_TOTAL];  // 42.5 MB

// ============================ helpers ============================
__device__ __forceinline__ uint32_t smem_u32(const void* p) {
    uint32_t a;
    asm("{ .reg .u64 t; cvta.to.shared.u64 t, %1; cvt.u32.u64 %0, t; }"
        : "=r"(a) : "l"(p));
    return a;
}

#define SW128(o) ((o) ^ (((o) >> 3) & 0x70))

__device__ __forceinline__ void cp16(uint32_t saddr, const void* g) {
    asm volatile("cp.async.cg.shared.global [%0], [%1], 16;"
                 :: "r"(saddr), "l"(g) : "memory");
}
#define CP_COMMIT() asm volatile("cp.async.commit_group;" ::: "memory")
#define CP_WAIT0()  asm volatile("cp.async.wait_group 0;" ::: "memory")
#define CP_WAIT1()  asm volatile("cp.async.wait_group 1;" ::: "memory")

#define LDSM_X4(r, addr) \
    asm volatile("ldmatrix.sync.aligned.m8n8.x4.shared.b16 {%0,%1,%2,%3}, [%4];" \
        : "=r"((r)[0]), "=r"((r)[1]), "=r"((r)[2]), "=r"((r)[3]) : "r"(addr))

#define MMA16816(d, a, b0, b1) \
    asm volatile("mma.sync.aligned.m16n8k16.row.col.f32.bf16.bf16.f32 " \
        "{%0,%1,%2,%3}, {%4,%5,%6,%7}, {%8,%9}, {%0,%1,%2,%3};" \
        : "+f"((d)[0]), "+f"((d)[1]), "+f"((d)[2]), "+f"((d)[3]) \
        : "r"((a)[0]), "r"((a)[1]), "r"((a)[2]), "r"((a)[3]), "r"(b0), "r"(b1))

// ============================ Quantize ============================
// Single launch over BOTH tensors. Block-staged, 256 groups per block.
// Exact: power-of-two scaling, <=8 significand bits -> exact in bf16.
#define NBLK_IN ((M_TOTAL * K_TOTAL) / (GSIZE * 256))   // 4096
#define NBLK_W  ((N_TOTAL * K_TOTAL) / (GSIZE * 256))   // 2304

__global__ void __launch_bounds__(256) bfp_quant(const float* __restrict__ inp,
                                                 const float* __restrict__ wgt,
                                                 __nv_bfloat16* __restrict__ qx,
                                                 __nv_bfloat16* __restrict__ qw) {
    __shared__ float s[9216];
    const int tid = threadIdx.x;
    const int blk = blockIdx.x;
    const bool is_w = (blk >= NBLK_IN);
    const float* in = is_w ? wgt : inp;
    __nv_bfloat16* out = is_w ? qw : qx;
    const size_t base = (size_t)(is_w ? blk - NBLK_IN : blk) * 9216;

    const float4* in4 = (const float4*)(in + base);
    float4* s4 = (float4*)s;
    #pragma unroll
    for (int j = 0; j < 9; ++j)
        s4[j * 256 + tid] = in4[j * 256 + tid];
    __syncthreads();

    float4 v[9];
    const float4* g4 = (const float4*)(s + tid * GSIZE);
    float m = 0.0f;
    #pragma unroll
    for (int i = 0; i < 9; ++i) {
        v[i] = g4[i];
        m = fmaxf(m, fmaxf(fmaxf(fabsf(v[i].x), fabsf(v[i].y)),
                           fmaxf(fabsf(v[i].z), fabsf(v[i].w))));
    }
    if (m > 0.0f) {
        int e = (int)((__float_as_uint(m) >> 23) & 0xFF) - 127;
        float stp = __int_as_float((uint32_t)(e - 7 + 127) << 23);  // 2^(e-7)
        float inv = __int_as_float((uint32_t)(7 - e + 127) << 23);  // 2^(7-e)
        #pragma unroll
        for (int i = 0; i < 9; ++i) {
            v[i].x = truncf(v[i].x * inv) * stp;
            v[i].y = truncf(v[i].y * inv) * stp;
            v[i].z = truncf(v[i].z * inv) * stp;
            v[i].w = truncf(v[i].w * inv) * stp;
        }
    }
    __syncthreads();   // all reads of s done before overwrite

    __nv_bfloat162* s2 = (__nv_bfloat162*)s;
    #pragma unroll
    for (int i = 0; i < 9; ++i) {
        s2[tid * 18 + 2 * i]     = __nv_bfloat162(__float2bfloat16(v[i].x),
                                                  __float2bfloat16(v[i].y));
        s2[tid * 18 + 2 * i + 1] = __nv_bfloat162(__float2bfloat16(v[i].z),
                                                  __float2bfloat16(v[i].w));
    }
    __syncthreads();

    uint4* o4 = (uint4*)(out + base);
    const uint4* so4 = (const uint4*)s;
    #pragma unroll
    for (int j = 0; j < 4; ++j)
        o4[j * 256 + tid] = so4[j * 256 + tid];
    if (tid < 128) o4[1024 + tid] = so4[1024 + tid];
}

// ============================ GEMM ============================
// D = qx @ qw^T + bias   (TN: both operands K-major)
// R10 config (measured best: 907us, tensor=62.9%): CTA 128x128, BK=64,
// 256 threads = 8 warps (2M x 4N), warp tile 64x32, 2 CTAs/SM, 3-stage
// cp.async ring, prefetch distance 2, single launch grid (36,64).
// R12 trims: mainloop unrolled x3 (compile-time stage -> SMEM bases
// constant-fold, less ALU in the issue stream); bias prefetched at
// iter 70 so the epilogue's L2 latency overlaps the final MMAs.
#define BM 128
#define BN 128
#define BK 64
#define KITERS (K_TOTAL / BK)       // 72 (= 24 * 3)
#define A_BYTES 16384               // 128 rows x 128 B
#define B_BYTES 16384
#define STAGE_BYTES (A_BYTES + B_BYTES)   // 32768
#define NSTAGE 3
#define SMEM_BYTES (NSTAGE * STAGE_BYTES) // 98304 per CTA (x2 = 192KB/SM)

__global__ void __launch_bounds__(256, 2)
bfp_gemm(const float* __restrict__ bias, float* __restrict__ out) {
    extern __shared__ char smem[];
    const uint32_t sb = smem_u32(smem);
    const int tid  = threadIdx.x;
    const int wid  = tid >> 5;
    const int lane = tid & 31;
    const int n0 = blockIdx.x * BN;
    const int m0 = blockIdx.y * BM;

    const int m_warp = (wid & 1) * 64;   // 2 warps along M
    const int n_warp = (wid >> 1) * 32;  // 4 warps along N

    const __nv_bfloat16* Ag = g_qx + (size_t)m0 * K_TOTAL;
    const __nv_bfloat16* Bg = g_qw + (size_t)n0 * K_TOTAL;

    // loader: A[128x64] + B[128x64] bf16, SW128 rows of 128 B.
    const int ldr = tid >> 3;        // 0..31
    const int ldc = tid & 7;         // 16B chunk
    const uint32_t soff0 = SW128((uint32_t)(ldr * 128 + ldc * 16));
    auto load_tiles = [&](int it, uint32_t stage_base) {
        const __nv_bfloat16* Ak = Ag + it * BK;
        const __nv_bfloat16* Bk = Bg + it * BK;
        #pragma unroll
        for (int j = 0; j < 4; ++j) {
            int r = ldr + j * 32;
            cp16(stage_base + soff0 + j * 32 * 128,
                 Ak + (size_t)r * K_TOTAL + ldc * 8);
            cp16(stage_base + A_BYTES + soff0 + j * 32 * 128,
                 Bk + (size_t)r * K_TOTAL + ldc * 8);
        }
        CP_COMMIT();
    };

    float acc[4][4][4];
    #pragma unroll
    for (int i = 0; i < 4; ++i)
        #pragma unroll
        for (int j = 0; j < 4; ++j)
            #pragma unroll
            for (int c = 0; c < 4; ++c) acc[i][j][c] = 0.0f;

    load_tiles(0, sb);
    load_tiles(1, sb + STAGE_BYTES);

    // ldmatrix lane addressing
    const int r_in  = (lane & 7) + ((lane >> 3) & 1) * 8;
    const int khalf = lane >> 4;

    // SW128(row*128 + bc) == row*128 + (bc ^ ((row&7)<<4)) for bc < 128.
    uint32_t rbA[4], rbB[2];
    #pragma unroll
    for (int im = 0; im < 4; ++im) {
        int r = m_warp + im * 16 + r_in;
        rbA[im] = (uint32_t)(r * 128 + ((r & 7) << 4));
    }
    #pragma unroll
    for (int j2 = 0; j2 < 2; ++j2) {
        int r = n_warp + j2 * 16 + r_in;
        rbB[j2] = (uint32_t)(r * 128 + ((r & 7) << 4));
    }
    const uint32_t bc0 = (uint32_t)(khalf * 16);

// one k-iteration of compute on compile-time stage STG
#define COMPUTE_STAGE(STG)                                                    \
    do {                                                                      \
        const uint32_t aBase = sb + (uint32_t)((STG) * STAGE_BYTES);          \
        const uint32_t bBase = aBase + A_BYTES;                               \
        _Pragma("unroll")                                                     \
        for (int ks = 0; ks < 4; ++ks) {                                      \
            const uint32_t bc = bc0 ^ (uint32_t)(ks * 32);                    \
            uint32_t afr[4][4], bfr[2][4];                                    \
            _Pragma("unroll")                                                 \
            for (int im = 0; im < 4; ++im)                                    \
                LDSM_X4(afr[im], aBase + (rbA[im] ^ bc));                     \
            _Pragma("unroll")                                                 \
            for (int j2 = 0; j2 < 2; ++j2)                                    \
                LDSM_X4(bfr[j2], bBase + (rbB[j2] ^ bc));                     \
            _Pragma("unroll")                                                 \
            for (int im = 0; im < 4; ++im)                                    \
                _Pragma("unroll")                                             \
                for (int jn = 0; jn < 4; ++jn)                                \
                    MMA16816(acc[im][jn],                                     \
                             afr[im],                                         \
                             bfr[jn >> 1][jn & 1],                            \
                             bfr[jn >> 1][(jn & 1) + 2]);                     \
        }                                                                     \
    } while (0)

    // main loop: iters 0..68 in 23 unrolled blocks of 3 (stages 0,1,2)
    for (int it3 = 0; it3 < KITERS - 3; it3 += 3) {
        CP_WAIT1(); __syncthreads();
        load_tiles(it3 + 2, sb + 2 * STAGE_BYTES);
        COMPUTE_STAGE(0);

        CP_WAIT1(); __syncthreads();
        load_tiles(it3 + 3, sb);
        COMPUTE_STAGE(1);

        CP_WAIT1(); __syncthreads();
        load_tiles(it3 + 4, sb + STAGE_BYTES);
        COMPUTE_STAGE(2);
    }

    // tail: iters 69, 70, 71  (stages 0, 1, 2)
    const int row_t = lane >> 2;
    const int col_t = (lane & 3) * 2;
    float bx[4], by[4];

    CP_WAIT1(); __syncthreads();
    load_tiles(KITERS - 1, sb + 2 * STAGE_BYTES);   // it=69 loads 71
    COMPUTE_STAGE(0);

    CP_WAIT1(); __syncthreads();
    #pragma unroll
    for (int jn = 0; jn < 4; ++jn) {                // bias prefetch (it=70)
        const int gn = n0 + n_warp + jn * 8 + col_t;
        bx[jn] = __ldg(bias + gn);
        by[jn] = __ldg(bias + gn + 1);
    }
    COMPUTE_STAGE(1);

    CP_WAIT0(); __syncthreads();
    COMPUTE_STAGE(2);

#undef COMPUTE_STAGE

    // --- epilogue: direct register -> gmem float2 stores (+bias)
    #pragma unroll
    for (int jn = 0; jn < 4; ++jn) {
        const int gn = n0 + n_warp + jn * 8 + col_t;
        #pragma unroll
        for (int im = 0; im < 4; ++im) {
            const int gm = m0 + m_warp + im * 16 + row_t;
            float2 v0 = make_float2(acc[im][jn][0] + bx[jn], acc[im][jn][1] + by[jn]);
            float2 v1 = make_float2(acc[im][jn][2] + bx[jn], acc[im][jn][3] + by[jn]);
            *(float2*)&out[(size_t)gm * N_TOTAL + gn]       = v0;
            *(float2*)&out[(size_t)(gm + 8) * N_TOTAL + gn] = v1;
        }
    }
}

// ============================ launch ============================
extern "C" void kernel_launch(void* const* d_in, const int* in_sizes, int n_in,
                              void* d_out, int out_size) {
    const float* inp  = (const float*)d_in[0];
    const float* wgt  = (const float*)d_in[1];
    const float* bias = (const float*)d_in[2];
    float* out = (float*)d_out;

    void *qx_p = nullptr, *qw_p = nullptr;
    cudaGetSymbolAddress(&qx_p, g_qx);
    cudaGetSymbolAddress(&qw_p, g_qw);

    cudaFuncSetAttribute(bfp_gemm, cudaFuncAttributeMaxDynamicSharedMemorySize,
                         SMEM_BYTES);

    bfp_quant<<<NBLK_IN + NBLK_W, 256>>>(inp, wgt,
                                         (__nv_bfloat16*)qx_p,
                                         (__nv_bfloat16*)qw_p);

    dim3 grid(N_TOTAL / BN, M_TOTAL / BM);   // (36, 64)
    bfp_gemm<<<grid, 256, SMEM_BYTES>>>(bias, out);
}

// round 13
// speedup vs baseline: 1.0128x; 1.0105x over previous
#include <cuda_runtime.h>
#include <cuda_bf16.h>
#include <cstdint>

#define M_TOTAL 8192
#define K_TOTAL 4608
#define N_TOTAL 4608
#define GSIZE   36

// -------- device scratch (static: no allocation in kernel_launch) --------
__device__ __nv_bfloat16 g_qx[(size_t)M_TOTAL * K_TOTAL];  // 75.5 MB
__device__ __nv_bfloat16 g_qw[(size_t)N_TOTAL * K_TOTAL];  // 42.5 MB

// ============================ helpers ============================
__device__ __forceinline__ uint32_t smem_u32(const void* p) {
    uint32_t a;
    asm("{ .reg .u64 t; cvta.to.shared.u64 t, %1; cvt.u32.u64 %0, t; }"
        : "=r"(a) : "l"(p));
    return a;
}

#define SW128(o) ((o) ^ (((o) >> 3) & 0x70))

__device__ __forceinline__ void cp16(uint32_t saddr, const void* g) {
    asm volatile("cp.async.cg.shared.global [%0], [%1], 16;"
                 :: "r"(saddr), "l"(g) : "memory");
}
#define CP_COMMIT() asm volatile("cp.async.commit_group;" ::: "memory")
#define CP_WAIT0()  asm volatile("cp.async.wait_group 0;" ::: "memory")
#define CP_WAIT1()  asm volatile("cp.async.wait_group 1;" ::: "memory")

#define LDSM_X4(r, addr) \
    asm volatile("ldmatrix.sync.aligned.m8n8.x4.shared.b16 {%0,%1,%2,%3}, [%4];" \
        : "=r"((r)[0]), "=r"((r)[1]), "=r"((r)[2]), "=r"((r)[3]) : "r"(addr))

#define MMA16816(d, a, b0, b1) \
    asm volatile("mma.sync.aligned.m16n8k16.row.col.f32.bf16.bf16.f32 " \
        "{%0,%1,%2,%3}, {%4,%5,%6,%7}, {%8,%9}, {%0,%1,%2,%3};" \
        : "+f"((d)[0]), "+f"((d)[1]), "+f"((d)[2]), "+f"((d)[3]) \
        : "r"((a)[0]), "r"((a)[1]), "r"((a)[2]), "r"((a)[3]), "r"(b0), "r"(b1))

// ============================ Quantize ============================
// Single launch over BOTH tensors. Block-staged, 256 groups per block.
// Exact: power-of-two scaling, <=8 significand bits -> exact in bf16.
#define NBLK_IN ((M_TOTAL * K_TOTAL) / (GSIZE * 256))   // 4096
#define NBLK_W  ((N_TOTAL * K_TOTAL) / (GSIZE * 256))   // 2304

__global__ void __launch_bounds__(256) bfp_quant(const float* __restrict__ inp,
                                                 const float* __restrict__ wgt,
                                                 __nv_bfloat16* __restrict__ qx,
                                                 __nv_bfloat16* __restrict__ qw) {
    __shared__ float s[9216];
    const int tid = threadIdx.x;
    const int blk = blockIdx.x;
    const bool is_w = (blk >= NBLK_IN);
    const float* in = is_w ? wgt : inp;
    __nv_bfloat16* out = is_w ? qw : qx;
    const size_t base = (size_t)(is_w ? blk - NBLK_IN : blk) * 9216;

    const float4* in4 = (const float4*)(in + base);
    float4* s4 = (float4*)s;
    #pragma unroll
    for (int j = 0; j < 9; ++j)
        s4[j * 256 + tid] = in4[j * 256 + tid];
    __syncthreads();

    float4 v[9];
    const float4* g4 = (const float4*)(s + tid * GSIZE);
    float m = 0.0f;
    #pragma unroll
    for (int i = 0; i < 9; ++i) {
        v[i] = g4[i];
        m = fmaxf(m, fmaxf(fmaxf(fabsf(v[i].x), fabsf(v[i].y)),
                           fmaxf(fabsf(v[i].z), fabsf(v[i].w))));
    }
    if (m > 0.0f) {
        int e = (int)((__float_as_uint(m) >> 23) & 0xFF) - 127;
        float stp = __int_as_float((uint32_t)(e - 7 + 127) << 23);  // 2^(e-7)
        float inv = __int_as_float((uint32_t)(7 - e + 127) << 23);  // 2^(7-e)
        #pragma unroll
        for (int i = 0; i < 9; ++i) {
            v[i].x = truncf(v[i].x * inv) * stp;
            v[i].y = truncf(v[i].y * inv) * stp;
            v[i].z = truncf(v[i].z * inv) * stp;
            v[i].w = truncf(v[i].w * inv) * stp;
        }
    }
    __syncthreads();   // all reads of s done before overwrite

    __nv_bfloat162* s2 = (__nv_bfloat162*)s;
    #pragma unroll
    for (int i = 0; i < 9; ++i) {
        s2[tid * 18 + 2 * i]     = __nv_bfloat162(__float2bfloat16(v[i].x),
                                                  __float2bfloat16(v[i].y));
        s2[tid * 18 + 2 * i + 1] = __nv_bfloat162(__float2bfloat16(v[i].z),
                                                  __float2bfloat16(v[i].w));
    }
    __syncthreads();

    uint4* o4 = (uint4*)(out + base);
    const uint4* so4 = (const uint4*)s;
    #pragma unroll
    for (int j = 0; j < 4; ++j)
        o4[j * 256 + tid] = so4[j * 256 + tid];
    if (tid < 128) o4[1024 + tid] = so4[1024 + tid];
}

// ============================ GEMM ============================
// D = qx @ qw^T + bias   (TN: both operands K-major)
// R13: occupancy experiment -- 3 CTAs/SM (24 warps/SM, 6/SMSP).
// CTA tile 128x64, BK=64, 256 threads = 8 warps (4M x 2N), warp tile
// 32x32 (32 acc regs -> fits 84-reg cap). NSTAGE=3 x 24KB = 72KB/CTA
// (216KB/SM at occ 3). Mainloop ring identical to R10 (measured best).
#define BM 128
#define BN 64
#define BK 64
#define KITERS (K_TOTAL / BK)       // 72
#define A_BYTES 16384               // 128 rows x 128 B
#define B_BYTES 8192                // 64 rows x 128 B
#define STAGE_BYTES (A_BYTES + B_BYTES)   // 24576
#define NSTAGE 3
#define SMEM_BYTES (NSTAGE * STAGE_BYTES) // 73728 per CTA (x3 = 216KB/SM)

__global__ void __launch_bounds__(256, 3)
bfp_gemm(const float* __restrict__ bias, float* __restrict__ out) {
    extern __shared__ char smem[];
    const uint32_t sb = smem_u32(smem);
    const int tid  = threadIdx.x;
    const int wid  = tid >> 5;
    const int lane = tid & 31;
    const int n0 = blockIdx.x * BN;
    const int m0 = blockIdx.y * BM;

    const int m_warp = (wid & 3) * 32;   // 4 warps along M (128)
    const int n_warp = (wid >> 2) * 32;  // 2 warps along N (64)

    const __nv_bfloat16* Ag = g_qx + (size_t)m0 * K_TOTAL;
    const __nv_bfloat16* Bg = g_qw + (size_t)n0 * K_TOTAL;

    // loader: A[128x64] (4 chunks/thread) + B[64x64] (2 chunks/thread)
    const int ldr = tid >> 3;        // 0..31
    const int ldc = tid & 7;         // 16B chunk
    const uint32_t soff0 = SW128((uint32_t)(ldr * 128 + ldc * 16));
    auto load_tiles = [&](int it, int stage) {
        const __nv_bfloat16* Ak = Ag + it * BK;
        const __nv_bfloat16* Bk = Bg + it * BK;
        const uint32_t base = sb + (uint32_t)stage * STAGE_BYTES;
        #pragma unroll
        for (int j = 0; j < 4; ++j) {
            int r = ldr + j * 32;
            cp16(base + soff0 + j * 32 * 128,
                 Ak + (size_t)r * K_TOTAL + ldc * 8);
        }
        #pragma unroll
        for (int j = 0; j < 2; ++j) {
            int r = ldr + j * 32;
            cp16(base + A_BYTES + soff0 + j * 32 * 128,
                 Bk + (size_t)r * K_TOTAL + ldc * 8);
        }
        CP_COMMIT();
    };

    float acc[2][4][4];
    #pragma unroll
    for (int i = 0; i < 2; ++i)
        #pragma unroll
        for (int j = 0; j < 4; ++j)
            #pragma unroll
            for (int c = 0; c < 4; ++c) acc[i][j][c] = 0.0f;

    load_tiles(0, 0);
    load_tiles(1, 1);

    // ldmatrix lane addressing
    const int r_in  = (lane & 7) + ((lane >> 3) & 1) * 8;
    const int khalf = lane >> 4;

    // SW128(row*128 + bc) == row*128 + (bc ^ ((row&7)<<4)) for bc < 128.
    uint32_t rbA[2], rbB[2];
    #pragma unroll
    for (int im = 0; im < 2; ++im) {
        int r = m_warp + im * 16 + r_in;
        rbA[im] = (uint32_t)(r * 128 + ((r & 7) << 4));
    }
    #pragma unroll
    for (int j2 = 0; j2 < 2; ++j2) {
        int r = n_warp + j2 * 16 + r_in;
        rbB[j2] = (uint32_t)(r * 128 + ((r & 7) << 4));
    }
    const uint32_t bc0 = (uint32_t)(khalf * 16);

    int stage = 0;
    for (int it = 0; it < KITERS; ++it) {
        if (it + 1 < KITERS) { CP_WAIT1(); } else { CP_WAIT0(); }
        __syncthreads();       // group(it) data visible; reload slot free

        if (it + 2 < KITERS) {
            int ls = stage + 2; if (ls >= NSTAGE) ls -= NSTAGE;
            load_tiles(it + 2, ls);
        }

        const uint32_t aBase = sb + (uint32_t)stage * STAGE_BYTES;
        const uint32_t bBase = aBase + A_BYTES;

        #pragma unroll
        for (int ks = 0; ks < 4; ++ks) {
            const uint32_t bc = bc0 ^ (uint32_t)(ks * 32);
            uint32_t afr[2][4], bfr[2][4];
            #pragma unroll
            for (int im = 0; im < 2; ++im)
                LDSM_X4(afr[im], aBase + (rbA[im] ^ bc));
            #pragma unroll
            for (int j2 = 0; j2 < 2; ++j2)
                LDSM_X4(bfr[j2], bBase + (rbB[j2] ^ bc));
            #pragma unroll
            for (int im = 0; im < 2; ++im)
                #pragma unroll
                for (int jn = 0; jn < 4; ++jn)
                    MMA16816(acc[im][jn],
                             afr[im],
                             bfr[jn >> 1][jn & 1],
                             bfr[jn >> 1][(jn & 1) + 2]);
        }
        stage = (stage + 1 == NSTAGE) ? 0 : stage + 1;
    }

    // --- epilogue: direct register -> gmem float2 stores (+bias)
    const int row_t = lane >> 2;
    const int col_t = (lane & 3) * 2;
    #pragma unroll
    for (int jn = 0; jn < 4; ++jn) {
        const int gn = n0 + n_warp + jn * 8 + col_t;
        const float bx = __ldg(bias + gn);
        const float by = __ldg(bias + gn + 1);
        #pragma unroll
        for (int im = 0; im < 2; ++im) {
            const int gm = m0 + m_warp + im * 16 + row_t;
            float2 v0 = make_float2(acc[im][jn][0] + bx, acc[im][jn][1] + by);
            float2 v1 = make_float2(acc[im][jn][2] + bx, acc[im][jn][3] + by);
            *(float2*)&out[(size_t)gm * N_TOTAL + gn]       = v0;
            *(float2*)&out[(size_t)(gm + 8) * N_TOTAL + gn] = v1;
        }
    }
}

// ============================ launch ============================
extern "C" void kernel_launch(void* const* d_in, const int* in_sizes, int n_in,
                              void* d_out, int out_size) {
    const float* inp  = (const float*)d_in[0];
    const float* wgt  = (const float*)d_in[1];
    const float* bias = (const float*)d_in[2];
    float* out = (float*)d_out;

    void *qx_p = nullptr, *qw_p = nullptr;
    cudaGetSymbolAddress(&qx_p, g_qx);
    cudaGetSymbolAddress(&qw_p, g_qw);

    cudaFuncSetAttribute(bfp_gemm, cudaFuncAttributeMaxDynamicSharedMemorySize,
                         SMEM_BYTES);

    bfp_quant<<<NBLK_IN + NBLK_W, 256>>>(inp, wgt,
                                         (__nv_bfloat16*)qx_p,
                                         (__nv_bfloat16*)qw_p);

    dim3 grid(N_TOTAL / BN, M_TOTAL / BM);   // (72, 64)
    bfp_gemm<<<grid, 256, SMEM_BYTES>>>(bias, out);
}

// round 14
// speedup vs baseline: 1.0158x; 1.0030x over previous
#include <cuda_runtime.h>
#include <cuda_bf16.h>
#include <cstdint>

#define M_TOTAL 8192
#define K_TOTAL 4608
#define N_TOTAL 4608
#define GSIZE   36

// -------- device scratch (static: no allocation in kernel_launch) --------
__device__ __nv_bfloat16 g_qx[(size_t)M_TOTAL * K_TOTAL];  // 75.5 MB
__device__ __nv_bfloat16 g_qw[(size_t)N_TOTAL * K_TOTAL];  // 42.5 MB

// ============================ helpers ============================
__device__ __forceinline__ uint32_t smem_u32(const void* p) {
    uint32_t a;
    asm("{ .reg .u64 t; cvta.to.shared.u64 t, %1; cvt.u32.u64 %0, t; }"
        : "=r"(a) : "l"(p));
    return a;
}

#define SW128(o) ((o) ^ (((o) >> 3) & 0x70))

__device__ __forceinline__ void cp16(uint32_t saddr, const void* g) {
    asm volatile("cp.async.cg.shared.global [%0], [%1], 16;"
                 :: "r"(saddr), "l"(g) : "memory");
}
#define CP_COMMIT() asm volatile("cp.async.commit_group;" ::: "memory")
#define CP_WAIT0()  asm volatile("cp.async.wait_group 0;" ::: "memory")
#define CP_WAIT1()  asm volatile("cp.async.wait_group 1;" ::: "memory")

#define LDSM_X4(r, addr) \
    asm volatile("ldmatrix.sync.aligned.m8n8.x4.shared.b16 {%0,%1,%2,%3}, [%4];" \
        : "=r"((r)[0]), "=r"((r)[1]), "=r"((r)[2]), "=r"((r)[3]) : "r"(addr))

#define MMA16816(d, a, b0, b1) \
    asm volatile("mma.sync.aligned.m16n8k16.row.col.f32.bf16.bf16.f32 " \
        "{%0,%1,%2,%3}, {%4,%5,%6,%7}, {%8,%9}, {%0,%1,%2,%3};" \
        : "+f"((d)[0]), "+f"((d)[1]), "+f"((d)[2]), "+f"((d)[3]) \
        : "r"((a)[0]), "r"((a)[1]), "r"((a)[2]), "r"((a)[3]), "r"(b0), "r"(b1))

// ============================ Quantize ============================
// Single launch over BOTH tensors. 128 groups (4608 floats = 18 KB) per
// 128-thread block -> ~11 blocks/SM resident (was 5 at 36 KB), >2x the
// DRAM windows in flight across each barrier. Same conflict-free bank
// pattern (lane start banks 4t mod 32). Exact: power-of-two scaling,
// <=8 significand bits -> exact in bf16.
#define QBLK_GROUPS 128
#define QBLK_FLOATS (QBLK_GROUPS * GSIZE)                 // 4608
#define NBLK_IN ((M_TOTAL * K_TOTAL) / QBLK_FLOATS)       // 8192
#define NBLK_W  ((N_TOTAL * K_TOTAL) / QBLK_FLOATS)       // 4608

__global__ void __launch_bounds__(128) bfp_quant(const float* __restrict__ inp,
                                                 const float* __restrict__ wgt,
                                                 __nv_bfloat16* __restrict__ qx,
                                                 __nv_bfloat16* __restrict__ qw) {
    __shared__ float s[QBLK_FLOATS];
    const int tid = threadIdx.x;
    const int blk = blockIdx.x;
    const bool is_w = (blk >= NBLK_IN);
    const float* in = is_w ? wgt : inp;
    __nv_bfloat16* out = is_w ? qw : qx;
    const size_t base = (size_t)(is_w ? blk - NBLK_IN : blk) * QBLK_FLOATS;

    // coalesced load: 1152 float4 / 128 threads = 9 each
    const float4* in4 = (const float4*)(in + base);
    float4* s4 = (float4*)s;
    #pragma unroll
    for (int j = 0; j < 9; ++j)
        s4[j * 128 + tid] = in4[j * 128 + tid];
    __syncthreads();

    // one thread per group: 9 conflict-free float4 smem reads
    float4 v[9];
    const float4* g4 = (const float4*)(s + tid * GSIZE);
    float m = 0.0f;
    #pragma unroll
    for (int i = 0; i < 9; ++i) {
        v[i] = g4[i];
        m = fmaxf(m, fmaxf(fmaxf(fabsf(v[i].x), fabsf(v[i].y)),
                           fmaxf(fabsf(v[i].z), fabsf(v[i].w))));
    }
    if (m > 0.0f) {
        int e = (int)((__float_as_uint(m) >> 23) & 0xFF) - 127;
        float stp = __int_as_float((uint32_t)(e - 7 + 127) << 23);  // 2^(e-7)
        float inv = __int_as_float((uint32_t)(7 - e + 127) << 23);  // 2^(7-e)
        #pragma unroll
        for (int i = 0; i < 9; ++i) {
            v[i].x = truncf(v[i].x * inv) * stp;
            v[i].y = truncf(v[i].y * inv) * stp;
            v[i].z = truncf(v[i].z * inv) * stp;
            v[i].w = truncf(v[i].w * inv) * stp;
        }
    }
    __syncthreads();   // all reads of s done before overwrite

    __nv_bfloat162* s2 = (__nv_bfloat162*)s;
    #pragma unroll
    for (int i = 0; i < 9; ++i) {
        s2[tid * 18 + 2 * i]     = __nv_bfloat162(__float2bfloat16(v[i].x),
                                                  __float2bfloat16(v[i].y));
        s2[tid * 18 + 2 * i + 1] = __nv_bfloat162(__float2bfloat16(v[i].z),
                                                  __float2bfloat16(v[i].w));
    }
    __syncthreads();

    // 4608 bf16 = 9216 B = 576 uint4; 128 threads: 4 each + 64 extra
    uint4* o4 = (uint4*)(out + base);
    const uint4* so4 = (const uint4*)s;
    #pragma unroll
    for (int j = 0; j < 4; ++j)
        o4[j * 128 + tid] = so4[j * 128 + tid];
    if (tid < 64) o4[512 + tid] = so4[512 + tid];
}

// ============================ GEMM ============================
// D = qx @ qw^T + bias   (TN: both operands K-major)
// R10 configuration EXACT (measured best: 907us GEMM, tensor=62.9%):
// CTA: 128x128 tile, BK=64, 256 threads = 8 warps (2M x 4N), warp
// tile 64x32, 2 CTAs/SM, 3-stage cp.async ring, prefetch distance 2.
// ~63% tensor is the measured structural ceiling of legacy mma.sync on
// sm_103 (flat across occ 12.5-36.5%, 8 schedule variants).
#define BM 128
#define BN 128
#define BK 64
#define KITERS (K_TOTAL / BK)       // 72
#define A_BYTES 16384               // 128 rows x 128 B
#define B_BYTES 16384
#define STAGE_BYTES (A_BYTES + B_BYTES)   // 32768
#define NSTAGE 3
#define SMEM_BYTES (NSTAGE * STAGE_BYTES) // 98304 per CTA (x2 = 192KB/SM)

__global__ void __launch_bounds__(256, 2)
bfp_gemm(const float* __restrict__ bias, float* __restrict__ out) {
    extern __shared__ char smem[];
    const uint32_t sb = smem_u32(smem);
    const int tid  = threadIdx.x;
    const int wid  = tid >> 5;
    const int lane = tid & 31;
    const int n0 = blockIdx.x * BN;
    const int m0 = blockIdx.y * BM;

    const int m_warp = (wid & 1) * 64;   // 2 warps along M
    const int n_warp = (wid >> 1) * 32;  // 4 warps along N

    const __nv_bfloat16* Ag = g_qx + (size_t)m0 * K_TOTAL;
    const __nv_bfloat16* Bg = g_qw + (size_t)n0 * K_TOTAL;

    // loader: A[128x64] + B[128x64] bf16, SW128 rows of 128 B.
    const int ldr = tid >> 3;        // 0..31
    const int ldc = tid & 7;         // 16B chunk
    const uint32_t soff0 = SW128((uint32_t)(ldr * 128 + ldc * 16));
    auto load_tiles = [&](int it, int stage) {
        const __nv_bfloat16* Ak = Ag + it * BK;
        const __nv_bfloat16* Bk = Bg + it * BK;
        const uint32_t base = sb + (uint32_t)stage * STAGE_BYTES;
        #pragma unroll
        for (int j = 0; j < 4; ++j) {
            int r = ldr + j * 32;
            cp16(base + soff0 + j * 32 * 128,
                 Ak + (size_t)r * K_TOTAL + ldc * 8);
            cp16(base + A_BYTES + soff0 + j * 32 * 128,
                 Bk + (size_t)r * K_TOTAL + ldc * 8);
        }
        CP_COMMIT();
    };

    float acc[4][4][4];
    #pragma unroll
    for (int i = 0; i < 4; ++i)
        #pragma unroll
        for (int j = 0; j < 4; ++j)
            #pragma unroll
            for (int c = 0; c < 4; ++c) acc[i][j][c] = 0.0f;

    load_tiles(0, 0);
    load_tiles(1, 1);

    // ldmatrix lane addressing
    const int r_in  = (lane & 7) + ((lane >> 3) & 1) * 8;
    const int khalf = lane >> 4;

    // SW128(row*128 + bc) == row*128 + (bc ^ ((row&7)<<4)) for bc < 128.
    uint32_t rbA[4], rbB[2];
    #pragma unroll
    for (int im = 0; im < 4; ++im) {
        int r = m_warp + im * 16 + r_in;
        rbA[im] = (uint32_t)(r * 128 + ((r & 7) << 4));
    }
    #pragma unroll
    for (int j2 = 0; j2 < 2; ++j2) {
        int r = n_warp + j2 * 16 + r_in;
        rbB[j2] = (uint32_t)(r * 128 + ((r & 7) << 4));
    }
    const uint32_t bc0 = (uint32_t)(khalf * 16);

    int stage = 0;
    for (int it = 0; it < KITERS; ++it) {
        if (it + 1 < KITERS) { CP_WAIT1(); } else { CP_WAIT0(); }
        __syncthreads();       // all threads' group(it) copies visible;
                               // stage (it+2)%3 was last read at it-1

        if (it + 2 < KITERS) {
            int ls = stage + 2; if (ls >= NSTAGE) ls -= NSTAGE;
            load_tiles(it + 2, ls);
        }

        const uint32_t aBase = sb + (uint32_t)stage * STAGE_BYTES;
        const uint32_t bBase = aBase + A_BYTES;

        #pragma unroll
        for (int ks = 0; ks < 4; ++ks) {
            const uint32_t bc = bc0 ^ (uint32_t)(ks * 32);
            uint32_t afr[4][4], bfr[2][4];
            #pragma unroll
            for (int im = 0; im < 4; ++im)
                LDSM_X4(afr[im], aBase + (rbA[im] ^ bc));
            #pragma unroll
            for (int j2 = 0; j2 < 2; ++j2)
                LDSM_X4(bfr[j2], bBase + (rbB[j2] ^ bc));
            #pragma unroll
            for (int im = 0; im < 4; ++im)
                #pragma unroll
                for (int jn = 0; jn < 4; ++jn)
                    MMA16816(acc[im][jn],
                             afr[im],
                             bfr[jn >> 1][jn & 1],
                             bfr[jn >> 1][(jn & 1) + 2]);
        }
        stage = (stage + 1 == NSTAGE) ? 0 : stage + 1;
    }

    // --- epilogue: direct register -> gmem float2 stores (+bias)
    const int row_t = lane >> 2;
    const int col_t = (lane & 3) * 2;
    #pragma unroll
    for (int jn = 0; jn < 4; ++jn) {
        const int gn = n0 + n_warp + jn * 8 + col_t;
        const float bx = __ldg(bias + gn);
        const float by = __ldg(bias + gn + 1);
        #pragma unroll
        for (int im = 0; im < 4; ++im) {
            const int gm = m0 + m_warp + im * 16 + row_t;
            float2 v0 = make_float2(acc[im][jn][0] + bx, acc[im][jn][1] + by);
            float2 v1 = make_float2(acc[im][jn][2] + bx, acc[im][jn][3] + by);
            *(float2*)&out[(size_t)gm * N_TOTAL + gn]       = v0;
            *(float2*)&out[(size_t)(gm + 8) * N_TOTAL + gn] = v1;
        }
    }
}

// ============================ launch ============================
extern "C" void kernel_launch(void* const* d_in, const int* in_sizes, int n_in,
                              void* d_out, int out_size) {
    const float* inp  = (const float*)d_in[0];
    const float* wgt  = (const float*)d_in[1];
    const float* bias = (const float*)d_in[2];
    float* out = (float*)d_out;

    void *qx_p = nullptr, *qw_p = nullptr;
    cudaGetSymbolAddress(&qx_p, g_qx);
    cudaGetSymbolAddress(&qw_p, g_qw);

    cudaFuncSetAttribute(bfp_gemm, cudaFuncAttributeMaxDynamicSharedMemorySize,
                         SMEM_BYTES);

    bfp_quant<<<NBLK_IN + NBLK_W, 128>>>(inp, wgt,
                                         (__nv_bfloat16*)qx_p,
                                         (__nv_bfloat16*)qw_p);

    dim3 grid(N_TOTAL / BN, M_TOTAL / BM);   // (36, 64)
    bfp_gemm<<<grid, 256, SMEM_BYTES>>>(bias, out);
}